// round 14
// baseline (speedup 1.0000x reference)
#include <cuda_runtime.h>
#include <cstdint>

// FusedMultiPool: out[b,s,h,w] = max_k x[b, idx[s,k], h, w]
// x[32,256,64,64] f32, idx[128,8] i32, out[32,128,64,64] f32.
//
// R13: warp-specialized producer/consumer. R7-family post-mortem: L1-busy is
// pinned at the ~23.5us wavefront floor; the ~12us idle is per-tile
// wait_group+__syncthreads convergence of all 16 warps. Here 16 consumer
// warps (R7's exact unrolled compute) run free on per-stage mbarrier rings
// while 1 producer warp streams cp.async fills; no __syncthreads in the
// main loop, so warp skew no longer serializes the CTA.

#define BB 32
#define CC 256
#define HWP 4096                 // 64*64
#define SS 128
#define TT 32                    // hw strip width (floats); one tile = 32 KB
#define NTHREADS 544             // 16 consumer warps + 1 producer warp
#define NCWARPS 16
#define SETS_PER_WARP (SS / NCWARPS)  // 8

#define NTILES ((HWP / TT) * BB)     // 4096 flat tiles (b*128 + strip)
#define GRID 296                     // 148 SMs x 2 CTAs
#define TILE_FLOATS (CC * TT)        // 8192
#define TILE_BYTES (TILE_FLOATS * 4) // 32768
#define NBUF 3
#define IDX_BYTES (SS * 2 * 16)      // 4 KB
#define MBAR_OFF (NBUF * TILE_BYTES + IDX_BYTES)
#define SMEM_BYTES (MBAR_OFF + 64)   // + mbarrier block

// ---- PTX helpers -----------------------------------------------------------

__device__ __forceinline__ uint32_t smem_u32(const void* p) {
    return (uint32_t)__cvta_generic_to_shared(p);
}

__device__ __forceinline__ void cp_async16(uint32_t smem_dst, const void* gmem_src) {
    asm volatile("cp.async.cg.shared.global [%0], [%1], 16;\n"
                 :: "r"(smem_dst), "l"(gmem_src));
}

__device__ __forceinline__ void mbar_init(uint32_t addr, uint32_t count) {
    asm volatile("mbarrier.init.shared::cta.b64 [%0], %1;\n"
                 :: "r"(addr), "r"(count) : "memory");
}

__device__ __forceinline__ void mbar_arrive(uint32_t addr, uint32_t count) {
    asm volatile("mbarrier.arrive.shared::cta.b64 _, [%0], %1;\n"
                 :: "r"(addr), "r"(count) : "memory");
}

// Arrive on mbar when all of this thread's prior cp.async copies complete.
__device__ __forceinline__ void cp_async_mbar_arrive(uint32_t addr) {
    asm volatile("cp.async.mbarrier.arrive.noinc.shared::cta.b64 [%0];\n"
                 :: "r"(addr) : "memory");
}

__device__ __forceinline__ void mbar_wait(uint32_t addr, uint32_t parity) {
    asm volatile(
        "{\n\t"
        ".reg .pred P;\n\t"
        "WL_%=:\n\t"
        "mbarrier.try_wait.parity.acquire.cta.shared::cta.b64 P, [%0], %1, 0x989680;\n\t"
        "@P bra WD_%=;\n\t"
        "bra WL_%=;\n\t"
        "WD_%=:\n\t"
        "}"
        :: "r"(addr), "r"(parity) : "memory");
}

// ---- kernel ----------------------------------------------------------------

__global__ void __launch_bounds__(NTHREADS, 2)
fmp_kernel(const float* __restrict__ x,
           const int*   __restrict__ idx,
           float*       __restrict__ out)
{
    extern __shared__ __align__(16) unsigned char smem_raw[];
    float* bufs = reinterpret_cast<float*>(smem_raw);                 // 3 tiles
    int4*  sidx = reinterpret_cast<int4*>(smem_raw + NBUF * TILE_BYTES);
    const uint32_t mb    = smem_u32(smem_raw + MBAR_OFF);
    const uint32_t fullb = mb;            // full[s]  at mb + s*8
    const uint32_t empb  = mb + NBUF * 8; // empty[s] at mb + 24 + s*8

    const int t    = threadIdx.x;
    const int lane = t & 31;
    const int warp = t >> 5;
    const int g    = blockIdx.x;

    if (t == 0) {
        #pragma unroll
        for (int s = 0; s < NBUF; ++s) {
            mbar_init(fullb + s * 8, 32);   // 32 producer-lane completions
            mbar_init(empb  + s * 8, NCWARPS);
            mbar_arrive(empb + s * 8, NCWARPS);  // pre-arm: phase 0 complete
        }
    }
    __syncthreads();

    // Stage index table once, pre-scaled to byte offsets (c * 128).
    if (t < SS * 2) {
        int4 v = reinterpret_cast<const int4*>(idx)[t];
        v.x <<= 7; v.y <<= 7; v.z <<= 7; v.w <<= 7;
        sidx[t] = v;
    }
    __syncthreads();   // mbarriers + sidx visible; last CTA-wide barrier

    const int n = (NTILES - 1 - g) / GRID + 1;   // 13 or 14 tiles for this CTA

    if (warp == NCWARPS) {
        // ---------------- producer warp ----------------
        int stage = 0, phase = 0;
        for (int j = 0; j < n; ++j) {
            // fills j=0..2 pass instantly (pre-armed phase 0)
            mbar_wait(empb + stage * 8, phase);

            const int flat  = g + j * GRID;
            const int b     = flat >> 7;
            const int strip = flat & 127;
            const char* src = reinterpret_cast<const char*>(
                x + (size_t)b * CC * HWP + strip * TT);
            const uint32_t dst = smem_u32(bufs + stage * TILE_FLOATS);

            // 2048 16B chunks / 32 lanes = 64 cp.async per lane, coalesced
            // (8 chunks = one 128B channel row).
            #pragma unroll
            for (int k = 0; k < (TILE_BYTES / 16) / 32; ++k) {
                int chunk = lane + k * 32;
                int c = chunk >> 3;
                int q = chunk & 7;
                cp_async16(dst + chunk * 16,
                           src + (size_t)c * (HWP * 4) + q * 16);
            }
            cp_async_mbar_arrive(fullb + stage * 8);   // 32 lanes -> full

            if (++stage == NBUF) { stage = 0; phase ^= 1; }
        }
    } else {
        // ---------------- consumer warps ----------------
        int stage = 0, phase = 0;
        for (int i = 0; i < n; ++i) {
            mbar_wait(fullb + stage * 8, phase);

            const char* __restrict__ bb =
                reinterpret_cast<const char*>(bufs + stage * TILE_FLOATS)
                + lane * 4;
            const int flat  = g + i * GRID;
            const int b     = flat >> 7;
            const int strip = flat & 127;
            float* outb = out + (size_t)b * SS * HWP + strip * TT + lane;

            #pragma unroll
            for (int it = 0; it < SETS_PER_WARP; ++it) {
                const int s = warp * SETS_PER_WARP + it;
                const int4 r0 = sidx[s * 2 + 0];   // pre-scaled byte offsets
                const int4 r1 = sidx[s * 2 + 1];

                float v0 = *reinterpret_cast<const float*>(bb + r0.x);
                float v1 = *reinterpret_cast<const float*>(bb + r0.y);
                float v2 = *reinterpret_cast<const float*>(bb + r0.z);
                float v3 = *reinterpret_cast<const float*>(bb + r0.w);
                float v4 = *reinterpret_cast<const float*>(bb + r1.x);
                float v5 = *reinterpret_cast<const float*>(bb + r1.y);
                float v6 = *reinterpret_cast<const float*>(bb + r1.z);
                float v7 = *reinterpret_cast<const float*>(bb + r1.w);

                float m = fmaxf(fmaxf(fmaxf(v0, v1), fmaxf(v2, v3)),
                                fmaxf(fmaxf(v4, v5), fmaxf(v6, v7)));

                outb[(size_t)s * HWP] = m;   // 128 B coalesced STG per warp
            }

            __syncwarp();                    // all lanes done reading buf
            if (lane == 0)
                mbar_arrive(empb + stage * 8, 1);

            if (++stage == NBUF) { stage = 0; phase ^= 1; }
        }
    }
}

extern "C" void kernel_launch(void* const* d_in, const int* in_sizes, int n_in,
                              void* d_out, int out_size)
{
    const float* x   = (const float*)d_in[0];   // [32,256,64,64] f32
    const int*   idx = (const int*)d_in[1];     // [128,8] i32
    float*       out = (float*)d_out;           // [32,128,64,64] f32

    static bool attr_set = false;
    if (!attr_set) {
        cudaFuncSetAttribute(fmp_kernel,
                             cudaFuncAttributeMaxDynamicSharedMemorySize,
                             SMEM_BYTES);
        attr_set = true;
    }

    fmp_kernel<<<GRID, NTHREADS, SMEM_BYTES>>>(x, idx, out);
}

// round 15
// speedup vs baseline: 1.7969x; 1.7969x over previous
#include <cuda_runtime.h>
#include <cuda.h>
#include <cstdint>

// FusedMultiPool: out[b,s,h,w] = max_k x[b, idx[s,k], h, w]
// x[32,256,64,64] f32, idx[128,8] i32, out[32,128,64,64] f32.
//
// R14 = R7 skeleton (2 CTAs x 512, NBUF=3, one barrier per tile, unrolled
// 8-sets-per-warp compute) with the fill offloaded to TMA: one
// cp.async.bulk.tensor.2d per 32KB tile (box {32 floats, 256 rows}) instead
// of 2048 LDGSTS. Removes the fill's issue slots and ~256 L1 wavefronts per
// tile; the TMA engine keeps DRAM streaming independent of warp scheduling.
// R13 showed a 1-warp software producer throttles the stream; the TMA unit
// is the right "producer".

#define BB 32
#define CC 256
#define HWP 4096                 // 64*64
#define SS 128
#define TT 32                    // hw strip width (floats); one tile = 32 KB
#define NTHREADS 512
#define NWARPS (NTHREADS / 32)       // 16
#define SETS_PER_WARP (SS / NWARPS)  // 8

#define NTILES ((HWP / TT) * BB)     // 4096 flat tiles (b*128 + strip)
#define GRID 296                     // 148 SMs x 2 CTAs
#define TILE_FLOATS (CC * TT)        // 8192
#define TILE_BYTES (TILE_FLOATS * 4) // 32768
#define NBUF 3
#define IDX_BYTES (SS * 2 * 16)      // 4 KB
#define MBAR_OFF (NBUF * TILE_BYTES + IDX_BYTES)
#define SMEM_BYTES (MBAR_OFF + 64)

// ---- PTX helpers -----------------------------------------------------------

__device__ __forceinline__ uint32_t smem_u32(const void* p) {
    return (uint32_t)__cvta_generic_to_shared(p);
}

__device__ __forceinline__ void mbar_init(uint32_t addr, uint32_t count) {
    asm volatile("mbarrier.init.shared::cta.b64 [%0], %1;\n"
                 :: "r"(addr), "r"(count) : "memory");
}

__device__ __forceinline__ void mbar_expect_tx(uint32_t addr, uint32_t bytes) {
    asm volatile("mbarrier.arrive.expect_tx.shared::cta.b64 _, [%0], %1;\n"
                 :: "r"(addr), "r"(bytes) : "memory");
}

__device__ __forceinline__ void mbar_wait(uint32_t addr, uint32_t parity) {
    asm volatile(
        "{\n\t"
        ".reg .pred P;\n\t"
        "WL_%=:\n\t"
        "mbarrier.try_wait.parity.acquire.cta.shared::cta.b64 P, [%0], %1, 0x989680;\n\t"
        "@P bra WD_%=;\n\t"
        "bra WL_%=;\n\t"
        "WD_%=:\n\t"
        "}"
        :: "r"(addr), "r"(parity) : "memory");
}

__device__ __forceinline__ void tma_load_2d(uint32_t smem_dst,
                                            const CUtensorMap* tmap,
                                            int cx, int cy, uint32_t mbar) {
    asm volatile(
        "cp.async.bulk.tensor.2d.shared::cta.global.tile.mbarrier::complete_tx::bytes "
        "[%0], [%1, {%2, %3}], [%4];\n"
        :: "r"(smem_dst), "l"(tmap), "r"(cx), "r"(cy), "r"(mbar) : "memory");
}

// ---- kernel ----------------------------------------------------------------

__global__ void __launch_bounds__(NTHREADS, 2)
fmp_kernel(const __grid_constant__ CUtensorMap tmap,
           const int*   __restrict__ idx,
           float*       __restrict__ out)
{
    extern __shared__ __align__(128) unsigned char smem_raw[];
    float* bufs = reinterpret_cast<float*>(smem_raw);                 // 3 tiles
    int4*  sidx = reinterpret_cast<int4*>(smem_raw + NBUF * TILE_BYTES);
    const uint32_t fullb = smem_u32(smem_raw + MBAR_OFF);  // full[s] at +s*8

    const int t    = threadIdx.x;
    const int lane = t & 31;
    const int warp = t >> 5;
    const int g    = blockIdx.x;

    if (t == 0) {
        #pragma unroll
        for (int s = 0; s < NBUF; ++s)
            mbar_init(fullb + s * 8, 1);
    }

    // Stage index table once, pre-scaled to byte offsets (c * 128).
    if (t < SS * 2) {
        int4 v = reinterpret_cast<const int4*>(idx)[t];
        v.x <<= 7; v.y <<= 7; v.z <<= 7; v.w <<= 7;
        sidx[t] = v;
    }
    __syncthreads();   // mbarriers + sidx visible

    const int n = (NTILES - 1 - g) / GRID + 1;   // 13 or 14 tiles for this CTA

    // Prologue: TMA fills for tiles 0 and 1 (stages 0, 1).
    if (t == 0) {
        #pragma unroll
        for (int j = 0; j < 2; ++j) {
            if (j < n) {
                const int flat  = g + j * GRID;
                const int b     = flat >> 7;
                const int strip = flat & 127;
                mbar_expect_tx(fullb + j * 8, TILE_BYTES);
                tma_load_2d(smem_u32(bufs + j * TILE_FLOATS), &tmap,
                            strip * TT, b * CC, fullb + j * 8);
            }
        }
    }

    int st = 0, ph = 0;
    for (int i = 0; i < n; ++i) {
        mbar_wait(fullb + st * 8, ph);   // tile i landed (TMA writes acquired)
        __syncthreads();                 // all warps past wait; buf i-1 free

        // Issue TMA fill for tile i+2 into the stage freed by tile i-1.
        if (t == 0 && i + 2 < n) {
            int s2 = st + 2; if (s2 >= NBUF) s2 -= NBUF;
            const int flat  = g + (i + 2) * GRID;
            const int b     = flat >> 7;
            const int strip = flat & 127;
            mbar_expect_tx(fullb + s2 * 8, TILE_BYTES);
            tma_load_2d(smem_u32(bufs + s2 * TILE_FLOATS), &tmap,
                        strip * TT, b * CC, fullb + s2 * 8);
        }

        // Compute tile i: warp covers sets {8*warp .. 8*warp+7}, lane <-> hw.
        const char* __restrict__ bb =
            reinterpret_cast<const char*>(bufs + st * TILE_FLOATS) + lane * 4;
        const int flat  = g + i * GRID;
        const int b     = flat >> 7;
        const int strip = flat & 127;
        float* outb = out + (size_t)b * SS * HWP + strip * TT + lane;

        #pragma unroll
        for (int it = 0; it < SETS_PER_WARP; ++it) {
            const int s = warp * SETS_PER_WARP + it;
            const int4 r0 = sidx[s * 2 + 0];     // pre-scaled byte offsets
            const int4 r1 = sidx[s * 2 + 1];

            float v0 = *reinterpret_cast<const float*>(bb + r0.x);
            float v1 = *reinterpret_cast<const float*>(bb + r0.y);
            float v2 = *reinterpret_cast<const float*>(bb + r0.z);
            float v3 = *reinterpret_cast<const float*>(bb + r0.w);
            float v4 = *reinterpret_cast<const float*>(bb + r1.x);
            float v5 = *reinterpret_cast<const float*>(bb + r1.y);
            float v6 = *reinterpret_cast<const float*>(bb + r1.z);
            float v7 = *reinterpret_cast<const float*>(bb + r1.w);

            float m = fmaxf(fmaxf(fmaxf(v0, v1), fmaxf(v2, v3)),
                            fmaxf(fmaxf(v4, v5), fmaxf(v6, v7)));

            outb[(size_t)s * HWP] = m;           // 128 B coalesced STG per warp
        }

        if (++st == NBUF) { st = 0; ph ^= 1; }
    }
}

// ---- host ------------------------------------------------------------------

typedef CUresult (*EncodeTiledFn)(
    CUtensorMap*, CUtensorMapDataType, cuuint32_t, void*,
    const cuuint64_t*, const cuuint64_t*, const cuuint32_t*, const cuuint32_t*,
    CUtensorMapInterleave, CUtensorMapSwizzle, CUtensorMapL2promotion,
    CUtensorMapFloatOOBfill);

extern "C" void kernel_launch(void* const* d_in, const int* in_sizes, int n_in,
                              void* d_out, int out_size)
{
    const float* x   = (const float*)d_in[0];   // [32,256,64,64] f32
    const int*   idx = (const int*)d_in[1];     // [128,8] i32
    float*       out = (float*)d_out;           // [32,128,64,64] f32

    static CUtensorMap tmap;
    static bool init_done = false;
    if (!init_done) {
        // Resolve driver API without a link-time -lcuda dependency.
        void* fn = nullptr;
        cudaDriverEntryPointQueryResult qr;
        cudaGetDriverEntryPointByVersion("cuTensorMapEncodeTiled", &fn,
                                         12000, cudaEnableDefault, &qr);
        EncodeTiledFn encode = (EncodeTiledFn)fn;

        // x viewed as 2D: [B*C rows = 8192] x [HWP = 4096 floats].
        // Box = one tile: 32 floats (128 B) x 256 rows (one batch's channels).
        cuuint64_t dims[2]    = { HWP, (cuuint64_t)BB * CC };
        cuuint64_t strides[1] = { HWP * sizeof(float) };
        cuuint32_t box[2]     = { TT, CC };
        cuuint32_t estr[2]    = { 1, 1 };
        encode(&tmap, CU_TENSOR_MAP_DATA_TYPE_FLOAT32, 2, (void*)x,
               dims, strides, box, estr,
               CU_TENSOR_MAP_INTERLEAVE_NONE, CU_TENSOR_MAP_SWIZZLE_NONE,
               CU_TENSOR_MAP_L2_PROMOTION_L2_128B,
               CU_TENSOR_MAP_FLOAT_OOB_FILL_NONE);

        cudaFuncSetAttribute(fmp_kernel,
                             cudaFuncAttributeMaxDynamicSharedMemorySize,
                             SMEM_BYTES);
        init_done = true;
    }

    fmp_kernel<<<GRID, NTHREADS, SMEM_BYTES>>>(tmap, idx, out);
}

// round 16
// speedup vs baseline: 1.8108x; 1.0077x over previous
#include <cuda_runtime.h>
#include <cuda.h>
#include <cstdint>

// FusedMultiPool: out[b,s,h,w] = max_k x[b, idx[s,k], h, w]
// x[32,256,64,64] f32, idx[128,8] i32, out[32,128,64,64] f32.
//
// R14 = R7 skeleton (2 CTAs x 512, NBUF=3, one barrier per tile, unrolled
// 8-sets-per-warp compute) with the fill offloaded to TMA: one
// cp.async.bulk.tensor.2d per 32KB tile (box {32 floats, 256 rows}) instead
// of 2048 LDGSTS. Removes the fill's issue slots and ~256 L1 wavefronts per
// tile; the TMA engine keeps DRAM streaming independent of warp scheduling.
// R13 showed a 1-warp software producer throttles the stream; the TMA unit
// is the right "producer".

#define BB 32
#define CC 256
#define HWP 4096                 // 64*64
#define SS 128
#define TT 32                    // hw strip width (floats); one tile = 32 KB
#define NTHREADS 512
#define NWARPS (NTHREADS / 32)       // 16
#define SETS_PER_WARP (SS / NWARPS)  // 8

#define NTILES ((HWP / TT) * BB)     // 4096 flat tiles (b*128 + strip)
#define GRID 296                     // 148 SMs x 2 CTAs
#define TILE_FLOATS (CC * TT)        // 8192
#define TILE_BYTES (TILE_FLOATS * 4) // 32768
#define NBUF 3
#define IDX_BYTES (SS * 2 * 16)      // 4 KB
#define MBAR_OFF (NBUF * TILE_BYTES + IDX_BYTES)
#define SMEM_BYTES (MBAR_OFF + 64)

// ---- PTX helpers -----------------------------------------------------------

__device__ __forceinline__ uint32_t smem_u32(const void* p) {
    return (uint32_t)__cvta_generic_to_shared(p);
}

__device__ __forceinline__ void mbar_init(uint32_t addr, uint32_t count) {
    asm volatile("mbarrier.init.shared::cta.b64 [%0], %1;\n"
                 :: "r"(addr), "r"(count) : "memory");
}

__device__ __forceinline__ void mbar_expect_tx(uint32_t addr, uint32_t bytes) {
    asm volatile("mbarrier.arrive.expect_tx.shared::cta.b64 _, [%0], %1;\n"
                 :: "r"(addr), "r"(bytes) : "memory");
}

__device__ __forceinline__ void mbar_wait(uint32_t addr, uint32_t parity) {
    asm volatile(
        "{\n\t"
        ".reg .pred P;\n\t"
        "WL_%=:\n\t"
        "mbarrier.try_wait.parity.acquire.cta.shared::cta.b64 P, [%0], %1, 0x989680;\n\t"
        "@P bra WD_%=;\n\t"
        "bra WL_%=;\n\t"
        "WD_%=:\n\t"
        "}"
        :: "r"(addr), "r"(parity) : "memory");
}

__device__ __forceinline__ void tma_load_2d(uint32_t smem_dst,
                                            const CUtensorMap* tmap,
                                            int cx, int cy, uint32_t mbar) {
    asm volatile(
        "cp.async.bulk.tensor.2d.shared::cta.global.tile.mbarrier::complete_tx::bytes "
        "[%0], [%1, {%2, %3}], [%4];\n"
        :: "r"(smem_dst), "l"(tmap), "r"(cx), "r"(cy), "r"(mbar) : "memory");
}

// ---- kernel ----------------------------------------------------------------

__global__ void __launch_bounds__(NTHREADS, 2)
fmp_kernel(const __grid_constant__ CUtensorMap tmap,
           const int*   __restrict__ idx,
           float*       __restrict__ out)
{
    extern __shared__ __align__(128) unsigned char smem_raw[];
    float* bufs = reinterpret_cast<float*>(smem_raw);                 // 3 tiles
    int4*  sidx = reinterpret_cast<int4*>(smem_raw + NBUF * TILE_BYTES);
    const uint32_t fullb = smem_u32(smem_raw + MBAR_OFF);  // full[s] at +s*8

    const int t    = threadIdx.x;
    const int lane = t & 31;
    const int warp = t >> 5;
    const int g    = blockIdx.x;

    if (t == 0) {
        #pragma unroll
        for (int s = 0; s < NBUF; ++s)
            mbar_init(fullb + s * 8, 1);
    }

    // Stage index table once, pre-scaled to byte offsets (c * 128).
    if (t < SS * 2) {
        int4 v = reinterpret_cast<const int4*>(idx)[t];
        v.x <<= 7; v.y <<= 7; v.z <<= 7; v.w <<= 7;
        sidx[t] = v;
    }
    __syncthreads();   // mbarriers + sidx visible

    const int n = (NTILES - 1 - g) / GRID + 1;   // 13 or 14 tiles for this CTA

    // Prologue: TMA fills for tiles 0 and 1 (stages 0, 1).
    if (t == 0) {
        #pragma unroll
        for (int j = 0; j < 2; ++j) {
            if (j < n) {
                const int flat  = g + j * GRID;
                const int b     = flat >> 7;
                const int strip = flat & 127;
                mbar_expect_tx(fullb + j * 8, TILE_BYTES);
                tma_load_2d(smem_u32(bufs + j * TILE_FLOATS), &tmap,
                            strip * TT, b * CC, fullb + j * 8);
            }
        }
    }

    int st = 0, ph = 0;
    for (int i = 0; i < n; ++i) {
        mbar_wait(fullb + st * 8, ph);   // tile i landed (TMA writes acquired)
        __syncthreads();                 // all warps past wait; buf i-1 free

        // Issue TMA fill for tile i+2 into the stage freed by tile i-1.
        if (t == 0 && i + 2 < n) {
            int s2 = st + 2; if (s2 >= NBUF) s2 -= NBUF;
            const int flat  = g + (i + 2) * GRID;
            const int b     = flat >> 7;
            const int strip = flat & 127;
            mbar_expect_tx(fullb + s2 * 8, TILE_BYTES);
            tma_load_2d(smem_u32(bufs + s2 * TILE_FLOATS), &tmap,
                        strip * TT, b * CC, fullb + s2 * 8);
        }

        // Compute tile i: warp covers sets {8*warp .. 8*warp+7}, lane <-> hw.
        const char* __restrict__ bb =
            reinterpret_cast<const char*>(bufs + st * TILE_FLOATS) + lane * 4;
        const int flat  = g + i * GRID;
        const int b     = flat >> 7;
        const int strip = flat & 127;
        float* outb = out + (size_t)b * SS * HWP + strip * TT + lane;

        #pragma unroll
        for (int it = 0; it < SETS_PER_WARP; ++it) {
            const int s = warp * SETS_PER_WARP + it;
            const int4 r0 = sidx[s * 2 + 0];     // pre-scaled byte offsets
            const int4 r1 = sidx[s * 2 + 1];

            float v0 = *reinterpret_cast<const float*>(bb + r0.x);
            float v1 = *reinterpret_cast<const float*>(bb + r0.y);
            float v2 = *reinterpret_cast<const float*>(bb + r0.z);
            float v3 = *reinterpret_cast<const float*>(bb + r0.w);
            float v4 = *reinterpret_cast<const float*>(bb + r1.x);
            float v5 = *reinterpret_cast<const float*>(bb + r1.y);
            float v6 = *reinterpret_cast<const float*>(bb + r1.z);
            float v7 = *reinterpret_cast<const float*>(bb + r1.w);

            float m = fmaxf(fmaxf(fmaxf(v0, v1), fmaxf(v2, v3)),
                            fmaxf(fmaxf(v4, v5), fmaxf(v6, v7)));

            outb[(size_t)s * HWP] = m;           // 128 B coalesced STG per warp
        }

        if (++st == NBUF) { st = 0; ph ^= 1; }
    }
}

// ---- host ------------------------------------------------------------------

typedef CUresult (*EncodeTiledFn)(
    CUtensorMap*, CUtensorMapDataType, cuuint32_t, void*,
    const cuuint64_t*, const cuuint64_t*, const cuuint32_t*, const cuuint32_t*,
    CUtensorMapInterleave, CUtensorMapSwizzle, CUtensorMapL2promotion,
    CUtensorMapFloatOOBfill);

extern "C" void kernel_launch(void* const* d_in, const int* in_sizes, int n_in,
                              void* d_out, int out_size)
{
    const float* x   = (const float*)d_in[0];   // [32,256,64,64] f32
    const int*   idx = (const int*)d_in[1];     // [128,8] i32
    float*       out = (float*)d_out;           // [32,128,64,64] f32

    static CUtensorMap tmap;
    static bool init_done = false;
    if (!init_done) {
        // Resolve driver API without a link-time -lcuda dependency.
        void* fn = nullptr;
        cudaDriverEntryPointQueryResult qr;
        cudaGetDriverEntryPointByVersion("cuTensorMapEncodeTiled", &fn,
                                         12000, cudaEnableDefault, &qr);
        EncodeTiledFn encode = (EncodeTiledFn)fn;

        // x viewed as 2D: [B*C rows = 8192] x [HWP = 4096 floats].
        // Box = one tile: 32 floats (128 B) x 256 rows (one batch's channels).
        cuuint64_t dims[2]    = { HWP, (cuuint64_t)BB * CC };
        cuuint64_t strides[1] = { HWP * sizeof(float) };
        cuuint32_t box[2]     = { TT, CC };
        cuuint32_t estr[2]    = { 1, 1 };
        encode(&tmap, CU_TENSOR_MAP_DATA_TYPE_FLOAT32, 2, (void*)x,
               dims, strides, box, estr,
               CU_TENSOR_MAP_INTERLEAVE_NONE, CU_TENSOR_MAP_SWIZZLE_NONE,
               CU_TENSOR_MAP_L2_PROMOTION_L2_128B,
               CU_TENSOR_MAP_FLOAT_OOB_FILL_NONE);

        cudaFuncSetAttribute(fmp_kernel,
                             cudaFuncAttributeMaxDynamicSharedMemorySize,
                             SMEM_BYTES);
        init_done = true;
    }

    fmp_kernel<<<GRID, NTHREADS, SMEM_BYTES>>>(tmap, idx, out);
}